// round 1
// baseline (speedup 1.0000x reference)
#include <cuda_runtime.h>
#include <cuda_bf16.h>
#include <math.h>

// Problem dims (fixed by the reference)
#define BB 4096
#define UU 256
#define DD 128

#define ROWS 16         // rows of x per block
#define THREADS 256     // one thread per u column
#define KC 16           // k-chunk staged per iteration
#define NCHUNK (DD / KC) // 8
#define K2C (KC / 2)     // 8 float2 per chunk
#define UPAD 257

// per-u constants: {nb2, bw, sqrt(ww), unused}
__device__ float4 g_cons[UU];

// ---------------------------------------------------------------------------
// packed f32x2 FMA (Blackwell): 2 FLOPs per FMA-pipe issue
// ---------------------------------------------------------------------------
__device__ __forceinline__ float2 ffma2(float2 a, float2 b, float2 c) {
    unsigned long long ua = *reinterpret_cast<unsigned long long*>(&a);
    unsigned long long ub = *reinterpret_cast<unsigned long long*>(&b);
    unsigned long long uc = *reinterpret_cast<unsigned long long*>(&c);
    unsigned long long ur;
    asm("fma.rn.f32x2 %0, %1, %2, %3;" : "=l"(ur) : "l"(ua), "l"(ub), "l"(uc));
    return *reinterpret_cast<float2*>(&ur);
}

// ---------------------------------------------------------------------------
// Kernel A: per-u scalars. One block per u, 128 threads (= D).
// ---------------------------------------------------------------------------
__global__ void precompute_kernel(const float* __restrict__ W,
                                  const float* __restrict__ bias) {
    int u = blockIdx.x;
    int k = threadIdx.x;
    float b = bias[u * DD + k];
    float w = W[u * DD + k];
    float nb2 = b * b;
    float bw  = b * w;
    float ww  = w * w;
    #pragma unroll
    for (int s = 16; s > 0; s >>= 1) {
        nb2 += __shfl_xor_sync(0xffffffffu, nb2, s);
        bw  += __shfl_xor_sync(0xffffffffu, bw,  s);
        ww  += __shfl_xor_sync(0xffffffffu, ww,  s);
    }
    __shared__ float red[3][4];
    int wid = k >> 5, lane = k & 31;
    if (lane == 0) { red[0][wid] = nb2; red[1][wid] = bw; red[2][wid] = ww; }
    __syncthreads();
    if (k == 0) {
        float n2 = red[0][0] + red[0][1] + red[0][2] + red[0][3];
        float bw_ = red[1][0] + red[1][1] + red[1][2] + red[1][3];
        float ww_ = red[2][0] + red[2][1] + red[2][2] + red[2][3];
        g_cons[u] = make_float4(n2, bw_, sqrtf(ww_), 0.0f);
    }
}

// ---------------------------------------------------------------------------
// Kernel B: fused dual-GEMM + epilogue + row-softmax.
// Block = 16 rows x 256 u. u = threadIdx.x.
// ---------------------------------------------------------------------------
__global__ void __launch_bounds__(THREADS, 2)
main_kernel(const float* __restrict__ x,
            const float* __restrict__ W,
            const float* __restrict__ bias,
            float* __restrict__ out) {
    // smem layout (manually carved, 41152 B):
    //   [0      , 8192 )  xs2   : float2 [ROWS][DD/2]   (x tile)
    //   [8192   , 24640)  swt   : float2 [K2C][UPAD]    (W chunk, k-transposed)
    //   [24640  , 41088)  sbt   : float2 [K2C][UPAD]    (bias chunk, k-transposed)
    //   [41088  , 41152)  snv2  : float  [ROWS]
    //   slog (epilogue phase) : float [ROWS][UPAD] at offset 0 (reuses xs2/swt)
    __shared__ __align__(16) unsigned char smem_raw[41152];
    float2* xs2  = reinterpret_cast<float2*>(smem_raw);
    float2* swt  = reinterpret_cast<float2*>(smem_raw + 8192);
    float2* sbt  = reinterpret_cast<float2*>(smem_raw + 8192 + 16448);
    float*  snv2 = reinterpret_cast<float*>(smem_raw + 8192 + 2 * 16448);
    float*  slog = reinterpret_cast<float*>(smem_raw);

    const int tid = threadIdx.x;
    const int u   = tid;
    const int b0  = blockIdx.x * ROWS;

    // ---- stage x tile [ROWS][DD] as float2 pairs ----
    const float4* x4 = reinterpret_cast<const float4*>(x);
    #pragma unroll
    for (int i = 0; i < (ROWS * DD / 4) / THREADS; i++) {   // 2 iters
        int f4 = i * THREADS + tid;
        int r  = f4 >> 5;          // 32 float4 per row
        int j  = f4 & 31;
        float4 g = x4[(b0 + r) * (DD / 4) + j];
        xs2[r * (DD / 2) + 2 * j    ] = make_float2(g.x, g.y);
        xs2[r * (DD / 2) + 2 * j + 1] = make_float2(g.z, g.w);
    }
    __syncthreads();

    // ---- nv2 per row: 16 threads per row ----
    {
        int r = tid >> 4;
        int h = tid & 15;
        float s = 0.0f;
        #pragma unroll
        for (int j = 0; j < 4; j++) {
            float2 v = xs2[r * (DD / 2) + h + 16 * j];
            s += v.x * v.x + v.y * v.y;
        }
        #pragma unroll
        for (int sh = 8; sh > 0; sh >>= 1)
            s += __shfl_xor_sync(0xffffffffu, s, sh);
        if (h == 0) snv2[r] = s;
    }

    // ---- accumulators (packed over k) ----
    float2 accw[ROWS], accb[ROWS];
    #pragma unroll
    for (int r = 0; r < ROWS; r++) {
        accw[r] = make_float2(0.0f, 0.0f);
        accb[r] = make_float2(0.0f, 0.0f);
    }

    const float4* W4 = reinterpret_cast<const float4*>(W);
    const float4* B4 = reinterpret_cast<const float4*>(bias);

    for (int c = 0; c < NCHUNK; c++) {
        __syncthreads();
        // stage W/bias chunk transposed: swt[k2][u]
        #pragma unroll
        for (int i = 0; i < (UU * KC / 4) / THREADS; i++) {  // 4 iters
            int f4 = i * THREADS + tid;
            int uu = f4 >> 2;          // 4 float4 per row-chunk
            int j  = f4 & 3;
            float4 gw = W4[uu * (DD / 4) + c * 4 + j];
            float4 gb = B4[uu * (DD / 4) + c * 4 + j];
            swt[(2 * j    ) * UPAD + uu] = make_float2(gw.x, gw.y);
            swt[(2 * j + 1) * UPAD + uu] = make_float2(gw.z, gw.w);
            sbt[(2 * j    ) * UPAD + uu] = make_float2(gb.x, gb.y);
            sbt[(2 * j + 1) * UPAD + uu] = make_float2(gb.z, gb.w);
        }
        __syncthreads();

        #pragma unroll
        for (int k2 = 0; k2 < K2C; k2++) {
            float2 w2 = swt[k2 * UPAD + u];
            float2 b2 = sbt[k2 * UPAD + u];
            #pragma unroll
            for (int r = 0; r < ROWS; r++) {
                float2 xv = xs2[r * (DD / 2) + c * K2C + k2];
                accw[r] = ffma2(w2, xv, accw[r]);
                accb[r] = ffma2(b2, xv, accb[r]);
            }
        }
    }

    // ---- epilogue: scalar hyperbolic math per (r,u) ----
    float4 cs  = g_cons[u];
    float  nb2 = cs.x, bw = cs.y, sww = cs.z;
    float  beta = 1.0f - nb2;

    float lg[ROWS];
    #pragma unroll
    for (int r = 0; r < ROWS; r++) {
        float xw = accw[r].x + accw[r].y;
        float xb = accb[r].x + accb[r].y;
        float nv2 = snv2[r];
        float xy = -xb;
        float t2 = 2.0f * xy;
        float alpha = 1.0f + t2 + nv2;
        float dd = 1.0f + t2 + nb2 * nv2;
        float num = 2.0f * beta * (beta * xw - alpha * bw);     // pre /dd
        float smm = (alpha * alpha * nb2 + 2.0f * alpha * beta * xy
                     + beta * beta * nv2) / (dd * dd);
        float den = (1.0f - smm) * beta * sww;
        float arg = num / (dd * den);
        lg[r] = 2.0f * sww * asinhf(arg);
    }

    __syncthreads();   // done reading swt/sbt/xs2/snv2
    #pragma unroll
    for (int r = 0; r < ROWS; r++)
        slog[r * UPAD + u] = lg[r];
    __syncthreads();

    // ---- softmax: warp w handles rows 2w, 2w+1 ----
    int w    = tid >> 5;
    int lane = tid & 31;
    #pragma unroll
    for (int rr = 0; rr < 2; rr++) {
        int r = 2 * w + rr;
        float v[8];
        float m = -1e30f;
        #pragma unroll
        for (int j = 0; j < 8; j++) {
            v[j] = slog[r * UPAD + lane + 32 * j];
            m = fmaxf(m, v[j]);
        }
        #pragma unroll
        for (int sh = 16; sh > 0; sh >>= 1)
            m = fmaxf(m, __shfl_xor_sync(0xffffffffu, m, sh));
        float e[8];
        float s = 0.0f;
        #pragma unroll
        for (int j = 0; j < 8; j++) { e[j] = __expf(v[j] - m); s += e[j]; }
        #pragma unroll
        for (int sh = 16; sh > 0; sh >>= 1)
            s += __shfl_xor_sync(0xffffffffu, s, sh);
        float inv = 1.0f / s;
        #pragma unroll
        for (int j = 0; j < 8; j++)
            out[(b0 + r) * UU + lane + 32 * j] = e[j] * inv;
    }
}

// ---------------------------------------------------------------------------
extern "C" void kernel_launch(void* const* d_in, const int* in_sizes, int n_in,
                              void* d_out, int out_size) {
    const float* x    = (const float*)d_in[0];
    const float* W    = (const float*)d_in[1];
    const float* bias = (const float*)d_in[2];
    float* out = (float*)d_out;

    precompute_kernel<<<UU, DD>>>(W, bias);
    main_kernel<<<BB / ROWS, THREADS>>>(x, W, bias, out);
}

// round 2
// speedup vs baseline: 1.4917x; 1.4917x over previous
#include <cuda_runtime.h>
#include <cuda_bf16.h>
#include <math.h>

// Problem dims (fixed by the reference)
#define BB 4096
#define UU 256
#define DD 128

#define ROWS 16         // rows of x per block
#define THREADS 256     // one thread per u column
#define K4N (DD / 4)    // 32 float4-groups along k
#define UPAD 257

// per-u constants: {nb2, bw, sqrt(ww), unused}
__device__ float4 g_cons[UU];
// transposed+interleaved weights: [k4][u][{w,b}] -> float4
// index: (k4*UU + u)*2 + sel   (sel 0 = W quad, 1 = bias quad)   256 KB
__device__ float4 g_wtb[K4N * UU * 2];

// ---------------------------------------------------------------------------
// packed f32x2 FMA (Blackwell): 2 FMA per FMA-pipe issue
// ---------------------------------------------------------------------------
__device__ __forceinline__ float2 ffma2(float2 a, float2 b, float2 c) {
    unsigned long long ua = *reinterpret_cast<unsigned long long*>(&a);
    unsigned long long ub = *reinterpret_cast<unsigned long long*>(&b);
    unsigned long long uc = *reinterpret_cast<unsigned long long*>(&c);
    unsigned long long ur;
    asm("fma.rn.f32x2 %0, %1, %2, %3;" : "=l"(ur) : "l"(ua), "l"(ub), "l"(uc));
    return *reinterpret_cast<float2*>(&ur);
}

// ---------------------------------------------------------------------------
// Kernel A: per-u scalars + weight transpose. One block per u, 128 threads.
// ---------------------------------------------------------------------------
__global__ void precompute_kernel(const float* __restrict__ W,
                                  const float* __restrict__ bias) {
    int u = blockIdx.x;
    int k = threadIdx.x;
    __shared__ float sw[DD], sb[DD];
    __shared__ float red[3][4];

    float b = bias[u * DD + k];
    float w = W[u * DD + k];
    sw[k] = w;
    sb[k] = b;

    float nb2 = b * b;
    float bw  = b * w;
    float ww  = w * w;
    #pragma unroll
    for (int s = 16; s > 0; s >>= 1) {
        nb2 += __shfl_xor_sync(0xffffffffu, nb2, s);
        bw  += __shfl_xor_sync(0xffffffffu, bw,  s);
        ww  += __shfl_xor_sync(0xffffffffu, ww,  s);
    }
    int wid = k >> 5, lane = k & 31;
    if (lane == 0) { red[0][wid] = nb2; red[1][wid] = bw; red[2][wid] = ww; }
    __syncthreads();

    if (k == 0) {
        float n2  = red[0][0] + red[0][1] + red[0][2] + red[0][3];
        float bw_ = red[1][0] + red[1][1] + red[1][2] + red[1][3];
        float ww_ = red[2][0] + red[2][1] + red[2][2] + red[2][3];
        g_cons[u] = make_float4(n2, bw_, sqrtf(ww_), 0.0f);
    }

    // transpose/interleave into g_wtb
    if (k < K4N) {
        int k4 = k;
        g_wtb[(k4 * UU + u) * 2 + 0] =
            make_float4(sw[4 * k4], sw[4 * k4 + 1], sw[4 * k4 + 2], sw[4 * k4 + 3]);
    } else if (k < 2 * K4N) {
        int k4 = k - K4N;
        g_wtb[(k4 * UU + u) * 2 + 1] =
            make_float4(sb[4 * k4], sb[4 * k4 + 1], sb[4 * k4 + 2], sb[4 * k4 + 3]);
    }
}

// ---------------------------------------------------------------------------
// Kernel B: fused dual-GEMM + epilogue + row-softmax.
// Block = 16 rows x 256 u. u = threadIdx.x. No barriers in mainloop.
// ---------------------------------------------------------------------------
__global__ void __launch_bounds__(THREADS, 2)
main_kernel(const float* __restrict__ x,
            float* __restrict__ out) {
    // smem: xs4 (8192 B, offset 0) reused by slog (16448 B); snv2 after both.
    __shared__ __align__(16) unsigned char smem_raw[16448 + 64];
    float4* xs4  = reinterpret_cast<float4*>(smem_raw);            // [ROWS][32]
    float*  slog = reinterpret_cast<float*>(smem_raw);             // [ROWS][UPAD]
    float*  snv2 = reinterpret_cast<float*>(smem_raw + 16448);     // [ROWS]

    const int tid = threadIdx.x;
    const int u   = tid;
    const int b0  = blockIdx.x * ROWS;

    // ---- stage x tile [ROWS][DD] as float4 (k4-major) ----
    const float4* x4 = reinterpret_cast<const float4*>(x);
    #pragma unroll
    for (int i = 0; i < (ROWS * K4N) / THREADS; i++) {   // 2 iters
        int f4 = i * THREADS + tid;
        int r  = f4 >> 5;          // 32 float4 per row
        int j  = f4 & 31;
        xs4[r * K4N + j] = x4[(b0 + r) * K4N + j];
    }
    __syncthreads();

    // ---- nv2 per row: 16 threads per row ----
    {
        int r = tid >> 4;
        int h = tid & 15;
        float s = 0.0f;
        #pragma unroll
        for (int j = 0; j < 2; j++) {
            float4 v = xs4[r * K4N + h + 16 * j];
            s += v.x * v.x + v.y * v.y + v.z * v.z + v.w * v.w;
        }
        #pragma unroll
        for (int sh = 8; sh > 0; sh >>= 1)
            s += __shfl_xor_sync(0xffffffffu, s, sh);
        if (h == 0) snv2[r] = s;
    }

    // ---- accumulators ----
    float2 accw[ROWS], accb[ROWS];
    #pragma unroll
    for (int r = 0; r < ROWS; r++) {
        accw[r] = make_float2(0.0f, 0.0f);
        accb[r] = make_float2(0.0f, 0.0f);
    }

    // ---- mainloop: stream weights from L2, x from smem, no barriers ----
    const float4* pu = g_wtb + u * 2;    // + k4*512 per step
    float4 wq_n = pu[0];
    float4 bq_n = pu[1];

    #pragma unroll 4
    for (int k4 = 0; k4 < K4N; k4++) {
        float4 wq = wq_n;
        float4 bq = bq_n;
        if (k4 + 1 < K4N) {
            wq_n = pu[(k4 + 1) * (UU * 2)];
            bq_n = pu[(k4 + 1) * (UU * 2) + 1];
        }
        float2 wlo = make_float2(wq.x, wq.y), whi = make_float2(wq.z, wq.w);
        float2 blo = make_float2(bq.x, bq.y), bhi = make_float2(bq.z, bq.w);
        #pragma unroll
        for (int r = 0; r < ROWS; r++) {
            float4 xq = xs4[r * K4N + k4];
            float2 xlo = make_float2(xq.x, xq.y), xhi = make_float2(xq.z, xq.w);
            accw[r] = ffma2(wlo, xlo, accw[r]);
            accw[r] = ffma2(whi, xhi, accw[r]);
            accb[r] = ffma2(blo, xlo, accb[r]);
            accb[r] = ffma2(bhi, xhi, accb[r]);
        }
    }

    // ---- epilogue: scalar hyperbolic math per (r,u) ----
    float4 cs  = g_cons[u];
    float  nb2 = cs.x, bw = cs.y, sww = cs.z;
    float  beta = 1.0f - nb2;

    __syncthreads();   // snv2 visible; xs4 no longer needed (slog overlaps it)

    float lg[ROWS];
    #pragma unroll
    for (int r = 0; r < ROWS; r++) {
        float xw = accw[r].x + accw[r].y;
        float xb = accb[r].x + accb[r].y;
        float nv2 = snv2[r];
        float xy = -xb;
        float t2 = 2.0f * xy;
        float alpha = 1.0f + t2 + nv2;
        float dd = 1.0f + t2 + nb2 * nv2;
        float num = 2.0f * beta * (beta * xw - alpha * bw);
        float inv_dd = 1.0f / dd;
        float smm = (alpha * alpha * nb2 + 2.0f * alpha * beta * xy
                     + beta * beta * nv2) * inv_dd * inv_dd;
        float den = (1.0f - smm) * beta * sww * dd;
        float arg = num / den;
        // asinh(arg) = log(arg + sqrt(arg^2 + 1))
        float s = arg + sqrtf(fmaf(arg, arg, 1.0f));
        lg[r] = 2.0f * sww * __logf(s);
    }

    #pragma unroll
    for (int r = 0; r < ROWS; r++)
        slog[r * UPAD + u] = lg[r];
    __syncthreads();

    // ---- softmax: warp w handles rows 2w, 2w+1 ----
    int w    = tid >> 5;
    int lane = tid & 31;
    #pragma unroll
    for (int rr = 0; rr < 2; rr++) {
        int r = 2 * w + rr;
        float v[8];
        float m = -1e30f;
        #pragma unroll
        for (int j = 0; j < 8; j++) {
            v[j] = slog[r * UPAD + lane + 32 * j];
            m = fmaxf(m, v[j]);
        }
        #pragma unroll
        for (int sh = 16; sh > 0; sh >>= 1)
            m = fmaxf(m, __shfl_xor_sync(0xffffffffu, m, sh));
        float e[8];
        float s = 0.0f;
        #pragma unroll
        for (int j = 0; j < 8; j++) { e[j] = __expf(v[j] - m); s += e[j]; }
        #pragma unroll
        for (int sh = 16; sh > 0; sh >>= 1)
            s += __shfl_xor_sync(0xffffffffu, s, sh);
        float inv = 1.0f / s;
        #pragma unroll
        for (int j = 0; j < 8; j++)
            out[(b0 + r) * UU + lane + 32 * j] = e[j] * inv;
    }
}

// ---------------------------------------------------------------------------
extern "C" void kernel_launch(void* const* d_in, const int* in_sizes, int n_in,
                              void* d_out, int out_size) {
    const float* x    = (const float*)d_in[0];
    const float* W    = (const float*)d_in[1];
    const float* bias = (const float*)d_in[2];
    float* out = (float*)d_out;

    precompute_kernel<<<UU, DD>>>(W, bias);
    main_kernel<<<BB / ROWS, THREADS>>>(x, out);
}

// round 4
// speedup vs baseline: 1.6044x; 1.0755x over previous
#include <cuda_runtime.h>
#include <cuda_bf16.h>
#include <math.h>
#include <stdint.h>

// Problem dims
#define BB 4096
#define UU 256
#define DD 128

// GEMM: C[4096, 512] = A[4096, 384]bf16 . B[512, 384]bf16^T, fp32 accum
// K = 3*128 (hi*hi, hi*lo, lo*hi), N = 512 (256 W | 256 bias)
#define NCHUNK 6                 // K chunks of 64 bf16
#define A_CH_U4 1024             // 128 rows x 64 bf16 = 16KB per chunk (uint4)
#define A_MT_U4 (NCHUNK * A_CH_U4)
#define B_NT_U4 (NCHUNK * A_CH_U4)   // B tiles also 128 rows x 64
#define GEMM_SMEM 65536          // 2 x (16KB A + 16KB B)

__device__ float4 g_cons[UU];            // {nb2, bw, sqrt(ww), 0}
__device__ float  g_nv2[BB];
__device__ uint4  g_A[32 * A_MT_U4];     // 3 MB pre-swizzled A (32 mtiles)
__device__ uint4  g_B[4 * B_NT_U4];      // 384 KB pre-swizzled B (4 ntiles)
__device__ float  g_acc[BB * 512];       // 8 MB raw xw|xb

// ---------------------------------------------------------------------------
// PTX helpers (sm_80-compatible only: cp.async, ldmatrix, mma.sync)
// ---------------------------------------------------------------------------
__device__ __forceinline__ uint32_t smem_u32(const void* p) {
    uint32_t a;
    asm("{ .reg .u64 t; cvta.to.shared.u64 t, %1; cvt.u32.u64 %0, t; }"
        : "=r"(a) : "l"(p));
    return a;
}
#define CP16(dst, src) \
    asm volatile("cp.async.cg.shared.global [%0], [%1], 16;" \
                 :: "r"(dst), "l"(src) : "memory")
#define CP_COMMIT() asm volatile("cp.async.commit_group;" ::: "memory")
#define CP_WAIT1()  asm volatile("cp.async.wait_group 1;" ::: "memory")
#define CP_WAIT0()  asm volatile("cp.async.wait_group 0;" ::: "memory")
#define LDSM4(r0, r1, r2, r3, addr) \
    asm volatile("ldmatrix.sync.aligned.m8n8.x4.shared.b16 {%0,%1,%2,%3}, [%4];" \
                 : "=r"(r0), "=r"(r1), "=r"(r2), "=r"(r3) : "r"(addr))
#define MMA16816(d0, d1, d2, d3, a0, a1, a2, a3, b0, b1) \
    asm volatile("mma.sync.aligned.m16n8k16.row.col.f32.bf16.bf16.f32 " \
                 "{%0,%1,%2,%3}, {%4,%5,%6,%7}, {%8,%9}, {%0,%1,%2,%3};" \
                 : "+f"(d0), "+f"(d1), "+f"(d2), "+f"(d3) \
                 : "r"(a0), "r"(a1), "r"(a2), "r"(a3), "r"(b0), "r"(b1))

__device__ __forceinline__ void split_bf16(float v, __nv_bfloat16& hi, __nv_bfloat16& lo) {
    hi = __float2bfloat16(v);
    lo = __float2bfloat16(v - __bfloat162float(hi));
}

// ---------------------------------------------------------------------------
// prepWB: per-u constants + pre-swizzled B. grid 256 (u), block 128.
// B logical row n = which*256 + u (which 0=W, 1=bias). ntile = n>>7.
// chunk images: 128 rows x 64 bf16, off16 = (r>>3)*64 + (r&7)*8 + (k16 ^ (r&7))
// chunk order along K: {half, 2+half: lo, 4+half: hi} pairing A {hi, hi, lo}.
// ---------------------------------------------------------------------------
__global__ void prepWB_kernel(const float* __restrict__ W,
                              const float* __restrict__ bias) {
    int u = blockIdx.x;
    int k = threadIdx.x;
    __shared__ float sw[DD], sb[DD];
    __shared__ float red[3][4];

    float b = bias[u * DD + k];
    float w = W[u * DD + k];
    sw[k] = w;
    sb[k] = b;

    float nb2 = b * b, bw = b * w, ww = w * w;
    #pragma unroll
    for (int s = 16; s > 0; s >>= 1) {
        nb2 += __shfl_xor_sync(0xffffffffu, nb2, s);
        bw  += __shfl_xor_sync(0xffffffffu, bw,  s);
        ww  += __shfl_xor_sync(0xffffffffu, ww,  s);
    }
    int wid = k >> 5, lane = k & 31;
    if (lane == 0) { red[0][wid] = nb2; red[1][wid] = bw; red[2][wid] = ww; }
    __syncthreads();
    if (k == 0) {
        float n2  = red[0][0] + red[0][1] + red[0][2] + red[0][3];
        float bw_ = red[1][0] + red[1][1] + red[1][2] + red[1][3];
        float ww_ = red[2][0] + red[2][1] + red[2][2] + red[2][3];
        g_cons[u] = make_float4(n2, bw_, sqrtf(ww_), 0.0f);
    }

    if (k < 32) {
        int which = k >> 4;      // 0 = W, 1 = bias
        int kg    = k & 15;      // 16-element k group (8 bf16 per store)
        const float* s = which ? sb : sw;
        union { __nv_bfloat16 h[8]; uint4 v; } hi, lo;
        #pragma unroll
        for (int i = 0; i < 8; i++)
            split_bf16(s[kg * 8 + i], hi.h[i], lo.h[i]);

        int n = which * 256 + u;
        int ntile = n >> 7, nloc = n & 127;
        int half = kg >> 3, k16 = kg & 7;
        int off16 = (nloc >> 3) * 64 + (nloc & 7) * 8 + (k16 ^ (nloc & 7));
        uint4* base = g_B + ntile * B_NT_U4;
        base[(half)     * A_CH_U4 + off16] = hi.v;
        base[(2 + half) * A_CH_U4 + off16] = lo.v;
        base[(4 + half) * A_CH_U4 + off16] = hi.v;
    }
}

// ---------------------------------------------------------------------------
// prepA: x -> pre-swizzled A splits + per-row nv2. grid 256, block 256.
// ---------------------------------------------------------------------------
__global__ void prepA_kernel(const float* __restrict__ x) {
    int tid = threadIdx.x;
    int r  = tid >> 4;
    int kg = tid & 15;
    int row = blockIdx.x * 16 + r;

    const float4* x4 = reinterpret_cast<const float4*>(x) + row * 32 + kg * 2;
    float4 a = x4[0], c = x4[1];
    float v[8] = {a.x, a.y, a.z, a.w, c.x, c.y, c.z, c.w};

    float s = 0.0f;
    union { __nv_bfloat16 h[8]; uint4 q; } hi, lo;
    #pragma unroll
    for (int i = 0; i < 8; i++) {
        s += v[i] * v[i];
        split_bf16(v[i], hi.h[i], lo.h[i]);
    }
    #pragma unroll
    for (int sh = 8; sh > 0; sh >>= 1)
        s += __shfl_xor_sync(0xffffffffu, s, sh);
    if (kg == 0) g_nv2[row] = s;

    int mtile = row >> 7, rloc = row & 127;
    int half = kg >> 3, k16 = kg & 7;
    int off16 = (rloc >> 3) * 64 + (rloc & 7) * 8 + (k16 ^ (rloc & 7));
    uint4* base = g_A + mtile * A_MT_U4;
    base[(half)     * A_CH_U4 + off16] = hi.q;   // hi (pairs B hi)
    base[(2 + half) * A_CH_U4 + off16] = hi.q;   // hi (pairs B lo)
    base[(4 + half) * A_CH_U4 + off16] = lo.q;   // lo (pairs B hi)
}

// ---------------------------------------------------------------------------
// GEMM: grid (4 ntiles, 32 mtiles), block 256 (8 warps).
// Warp tile 64x32: wm = wid&1 (m0 = 64*wm), wn = wid>>1 (n0 = 32*wn).
// Double-buffered cp.async chunks (64 k each), ldmatrix + mma.m16n8k16 bf16.
// ---------------------------------------------------------------------------
__device__ __forceinline__ void issue_chunk(uint32_t sbase, const uint4* gA,
                                            const uint4* gB, int c, int tid) {
    uint32_t dA = sbase + (c & 1) * 32768;
    uint32_t dB = dA + 16384;
    const uint4* sa = gA + c * A_CH_U4;
    const uint4* sb = gB + c * A_CH_U4;
    #pragma unroll
    for (int i = 0; i < 4; i++) CP16(dA + (tid + 256 * i) * 16, sa + tid + 256 * i);
    #pragma unroll
    for (int i = 0; i < 4; i++) CP16(dB + (tid + 256 * i) * 16, sb + tid + 256 * i);
    CP_COMMIT();
}

__global__ void __launch_bounds__(256)
gemm_kernel() {
    extern __shared__ __align__(1024) char smem[];
    uint32_t sbase = smem_u32(smem);
    const int tid = threadIdx.x;
    const int wid = tid >> 5, lane = tid & 31;
    const int ntile = blockIdx.x, mtile = blockIdx.y;

    const uint4* gA = g_A + mtile * A_MT_U4;
    const uint4* gB = g_B + ntile * B_NT_U4;

    // per-lane ldmatrix geometry
    // A: x4 covers m16 x k16. row = m0 + (lane&15); ku-select = lane>>4.
    const int m0 = (wid & 1) * 64;
    const int n0 = (wid >> 1) * 32;
    const int rowa  = m0 + (lane & 15);
    const int abase = (rowa >> 3) * 64 + (rowa & 7) * 8;   // uint4 units
    const int aswz  = rowa & 7;
    const int akus  = lane >> 4;
    // B: x4 covers n16 x k16. row = n0 + (lane&7) + 8*(lane>>4); ku-sel = (lane>>3)&1.
    const int rowb  = n0 + (lane & 7) + ((lane >> 4) << 3);
    const int bbase = (rowb >> 3) * 64 + (rowb & 7) * 8;
    const int bswz  = rowb & 7;
    const int bkus  = (lane >> 3) & 1;

    float d[4][4][4];
    #pragma unroll
    for (int i = 0; i < 4; i++)
        #pragma unroll
        for (int j = 0; j < 4; j++)
            #pragma unroll
            for (int q = 0; q < 4; q++) d[i][j][q] = 0.0f;

    issue_chunk(sbase, gA, gB, 0, tid);

    #pragma unroll
    for (int c = 0; c < NCHUNK; c++) {
        if (c < NCHUNK - 1) {
            issue_chunk(sbase, gA, gB, c + 1, tid);
            CP_WAIT1();
        } else {
            CP_WAIT0();
        }
        __syncthreads();

        uint32_t aB = sbase + (c & 1) * 32768;
        uint32_t bB = aB + 16384;

        #pragma unroll
        for (int kk = 0; kk < 4; kk++) {
            uint32_t af[4][4];
            #pragma unroll
            for (int mf = 0; mf < 4; mf++) {
                uint32_t addr = aB + ((abase + mf * 128 +
                                       ((2 * kk + akus) ^ aswz)) << 4);
                LDSM4(af[mf][0], af[mf][1], af[mf][2], af[mf][3], addr);
            }
            uint32_t bf[2][4];
            #pragma unroll
            for (int h = 0; h < 2; h++) {
                uint32_t addr = bB + ((bbase + h * 128 +
                                       ((2 * kk + bkus) ^ bswz)) << 4);
                LDSM4(bf[h][0], bf[h][1], bf[h][2], bf[h][3], addr);
            }
            #pragma unroll
            for (int mf = 0; mf < 4; mf++)
                #pragma unroll
                for (int nf = 0; nf < 4; nf++)
                    MMA16816(d[mf][nf][0], d[mf][nf][1], d[mf][nf][2], d[mf][nf][3],
                             af[mf][0], af[mf][1], af[mf][2], af[mf][3],
                             bf[nf >> 1][(nf & 1) * 2], bf[nf >> 1][(nf & 1) * 2 + 1]);
        }
        __syncthreads();
    }

    // store D: d0,d1 -> (row, col..col+1); d2,d3 -> (row+8, ...)
    const int rbase = mtile * 128 + m0 + (lane >> 2);
    const int cbase = ntile * 128 + n0 + 2 * (lane & 3);
    #pragma unroll
    for (int mf = 0; mf < 4; mf++)
        #pragma unroll
        for (int nf = 0; nf < 4; nf++) {
            int row = rbase + mf * 16;
            int col = cbase + nf * 8;
            *reinterpret_cast<float2*>(&g_acc[row * 512 + col]) =
                make_float2(d[mf][nf][0], d[mf][nf][1]);
            *reinterpret_cast<float2*>(&g_acc[(row + 8) * 512 + col]) =
                make_float2(d[mf][nf][2], d[mf][nf][3]);
        }
}

// ---------------------------------------------------------------------------
// Epilogue: hyperbolic math + softmax. grid 256 (16 rows each), block 256.
// ---------------------------------------------------------------------------
#define UPAD 257
__global__ void __launch_bounds__(256, 2)
epilogue_kernel(float* __restrict__ out) {
    __shared__ float slog[16 * UPAD];
    const int u  = threadIdx.x;
    const int b0 = blockIdx.x * 16;

    float4 cs  = g_cons[u];
    float  nb2 = cs.x, bw = cs.y, sww = cs.z;
    float  beta = 1.0f - nb2;

    float lg[16];
    #pragma unroll
    for (int r = 0; r < 16; r++) {
        float xw  = g_acc[(b0 + r) * 512 + u];
        float xb  = g_acc[(b0 + r) * 512 + 256 + u];
        float nv2 = g_nv2[b0 + r];
        float xy = -xb;
        float t2 = 2.0f * xy;
        float alpha = 1.0f + t2 + nv2;
        float dd = 1.0f + t2 + nb2 * nv2;
        float num = 2.0f * beta * (beta * xw - alpha * bw);
        float inv_dd = 1.0f / dd;
        float smm = (alpha * alpha * nb2 + 2.0f * alpha * beta * xy
                     + beta * beta * nv2) * inv_dd * inv_dd;
        float den = (1.0f - smm) * beta * sww * dd;
        float arg = num / den;
        float s = arg + sqrtf(fmaf(arg, arg, 1.0f));
        lg[r] = 2.0f * sww * __logf(s);
    }
    #pragma unroll
    for (int r = 0; r < 16; r++)
        slog[r * UPAD + u] = lg[r];
    __syncthreads();

    int w = u >> 5, lane = u & 31;
    #pragma unroll
    for (int rr = 0; rr < 2; rr++) {
        int r = 2 * w + rr;
        float v[8];
        float m = -1e30f;
        #pragma unroll
        for (int j = 0; j < 8; j++) {
            v[j] = slog[r * UPAD + lane + 32 * j];
            m = fmaxf(m, v[j]);
        }
        #pragma unroll
        for (int sh = 16; sh > 0; sh >>= 1)
            m = fmaxf(m, __shfl_xor_sync(0xffffffffu, m, sh));
        float e[8], s = 0.0f;
        #pragma unroll
        for (int j = 0; j < 8; j++) { e[j] = __expf(v[j] - m); s += e[j]; }
        #pragma unroll
        for (int sh = 16; sh > 0; sh >>= 1)
            s += __shfl_xor_sync(0xffffffffu, s, sh);
        float inv = 1.0f / s;
        #pragma unroll
        for (int j = 0; j < 8; j++)
            out[(b0 + r) * UU + lane + 32 * j] = e[j] * inv;
    }
}

// ---------------------------------------------------------------------------
extern "C" void kernel_launch(void* const* d_in, const int* in_sizes, int n_in,
                              void* d_out, int out_size) {
    const float* x    = (const float*)d_in[0];
    const float* W    = (const float*)d_in[1];
    const float* bias = (const float*)d_in[2];
    float* out = (float*)d_out;

    cudaFuncSetAttribute(gemm_kernel,
                         cudaFuncAttributeMaxDynamicSharedMemorySize, GEMM_SMEM);

    prepWB_kernel<<<UU, DD>>>(W, bias);
    prepA_kernel<<<BB / 16, 256>>>(x);
    gemm_kernel<<<dim3(4, 32), 256, GEMM_SMEM>>>();
    epilogue_kernel<<<BB / 16, 256>>>(out);
}

// round 5
// speedup vs baseline: 1.9763x; 1.2318x over previous
#include <cuda_runtime.h>
#include <cuda_bf16.h>
#include <math.h>
#include <stdint.h>

// Problem dims
#define BB 4096
#define UU 256
#define DD 128

// GEMM: C[4096, 512] = A[4096, 384]bf16 . B[512, 384]bf16^T, fp32 accum
// K = 3*128 (hi*hi, hi*lo, lo*hi), N = 512 (256 W | 256 bias)
#define NCHUNK 6                 // K chunks of 64 bf16
#define A_CH_U4 1024             // 128 rows x 64 bf16 = 16KB per chunk (uint4)
#define A_MT_U4 (NCHUNK * A_CH_U4)
#define B_NT_U4 (NCHUNK * A_CH_U4)   // B tiles also 128 rows x 64
#define GEMM_SMEM 65536          // 2 x (16KB A + 16KB B)

__device__ float4 g_cons[UU];            // {nb2, bw, sqrt(ww), 0}
__device__ float  g_nv2[BB];
__device__ uint4  g_A[32 * A_MT_U4];     // 3 MB pre-swizzled A (32 mtiles)
__device__ uint4  g_B[4 * B_NT_U4];      // 384 KB pre-swizzled B (4 ntiles)
__device__ float  g_acc[BB * 512];       // 8 MB raw xw|xb

// ---------------------------------------------------------------------------
// PTX helpers (sm_80-compatible only: cp.async, ldmatrix, mma.sync)
// ---------------------------------------------------------------------------
__device__ __forceinline__ uint32_t smem_u32(const void* p) {
    uint32_t a;
    asm("{ .reg .u64 t; cvta.to.shared.u64 t, %1; cvt.u32.u64 %0, t; }"
        : "=r"(a) : "l"(p));
    return a;
}
#define CP16(dst, src) \
    asm volatile("cp.async.cg.shared.global [%0], [%1], 16;" \
                 :: "r"(dst), "l"(src) : "memory")
#define CP_COMMIT() asm volatile("cp.async.commit_group;" ::: "memory")
#define CP_WAIT1()  asm volatile("cp.async.wait_group 1;" ::: "memory")
#define CP_WAIT0()  asm volatile("cp.async.wait_group 0;" ::: "memory")
#define LDSM4(r0, r1, r2, r3, addr) \
    asm volatile("ldmatrix.sync.aligned.m8n8.x4.shared.b16 {%0,%1,%2,%3}, [%4];" \
                 : "=r"(r0), "=r"(r1), "=r"(r2), "=r"(r3) : "r"(addr))
#define MMA16816(d0, d1, d2, d3, a0, a1, a2, a3, b0, b1) \
    asm volatile("mma.sync.aligned.m16n8k16.row.col.f32.bf16.bf16.f32 " \
                 "{%0,%1,%2,%3}, {%4,%5,%6,%7}, {%8,%9}, {%0,%1,%2,%3};" \
                 : "+f"(d0), "+f"(d1), "+f"(d2), "+f"(d3) \
                 : "r"(a0), "r"(a1), "r"(a2), "r"(a3), "r"(b0), "r"(b1))

__device__ __forceinline__ float fast_sqrt(float v) {
    float r;
    asm("sqrt.approx.f32 %0, %1;" : "=f"(r) : "f"(v));
    return r;
}

__device__ __forceinline__ void split_bf16(float v, __nv_bfloat16& hi, __nv_bfloat16& lo) {
    hi = __float2bfloat16(v);
    lo = __float2bfloat16(v - __bfloat162float(hi));
}

// ---------------------------------------------------------------------------
// prepWB: per-u constants + pre-swizzled B. grid 256 (u), block 128.
// ---------------------------------------------------------------------------
__global__ void prepWB_kernel(const float* __restrict__ W,
                              const float* __restrict__ bias) {
    int u = blockIdx.x;
    int k = threadIdx.x;
    __shared__ float sw[DD], sb[DD];
    __shared__ float red[3][4];

    float b = bias[u * DD + k];
    float w = W[u * DD + k];
    sw[k] = w;
    sb[k] = b;

    float nb2 = b * b, bw = b * w, ww = w * w;
    #pragma unroll
    for (int s = 16; s > 0; s >>= 1) {
        nb2 += __shfl_xor_sync(0xffffffffu, nb2, s);
        bw  += __shfl_xor_sync(0xffffffffu, bw,  s);
        ww  += __shfl_xor_sync(0xffffffffu, ww,  s);
    }
    int wid = k >> 5, lane = k & 31;
    if (lane == 0) { red[0][wid] = nb2; red[1][wid] = bw; red[2][wid] = ww; }
    __syncthreads();
    if (k == 0) {
        float n2  = red[0][0] + red[0][1] + red[0][2] + red[0][3];
        float bw_ = red[1][0] + red[1][1] + red[1][2] + red[1][3];
        float ww_ = red[2][0] + red[2][1] + red[2][2] + red[2][3];
        g_cons[u] = make_float4(n2, bw_, sqrtf(ww_), 0.0f);
    }

    if (k < 32) {
        int which = k >> 4;      // 0 = W, 1 = bias
        int kg    = k & 15;      // 16-element k group (8 bf16 per store)
        const float* s = which ? sb : sw;
        union { __nv_bfloat16 h[8]; uint4 v; } hi, lo;
        #pragma unroll
        for (int i = 0; i < 8; i++)
            split_bf16(s[kg * 8 + i], hi.h[i], lo.h[i]);

        int n = which * 256 + u;
        int ntile = n >> 7, nloc = n & 127;
        int half = kg >> 3, k16 = kg & 7;
        int off16 = (nloc >> 3) * 64 + (nloc & 7) * 8 + (k16 ^ (nloc & 7));
        uint4* base = g_B + ntile * B_NT_U4;
        base[(half)     * A_CH_U4 + off16] = hi.v;
        base[(2 + half) * A_CH_U4 + off16] = lo.v;
        base[(4 + half) * A_CH_U4 + off16] = hi.v;
    }
}

// ---------------------------------------------------------------------------
// prepA: x -> pre-swizzled A splits + per-row nv2. grid 256, block 256.
// ---------------------------------------------------------------------------
__global__ void prepA_kernel(const float* __restrict__ x) {
    int tid = threadIdx.x;
    int r  = tid >> 4;
    int kg = tid & 15;
    int row = blockIdx.x * 16 + r;

    const float4* x4 = reinterpret_cast<const float4*>(x) + row * 32 + kg * 2;
    float4 a = x4[0], c = x4[1];
    float v[8] = {a.x, a.y, a.z, a.w, c.x, c.y, c.z, c.w};

    float s = 0.0f;
    union { __nv_bfloat16 h[8]; uint4 q; } hi, lo;
    #pragma unroll
    for (int i = 0; i < 8; i++) {
        s += v[i] * v[i];
        split_bf16(v[i], hi.h[i], lo.h[i]);
    }
    #pragma unroll
    for (int sh = 8; sh > 0; sh >>= 1)
        s += __shfl_xor_sync(0xffffffffu, s, sh);
    if (kg == 0) g_nv2[row] = s;

    int mtile = row >> 7, rloc = row & 127;
    int half = kg >> 3, k16 = kg & 7;
    int off16 = (rloc >> 3) * 64 + (rloc & 7) * 8 + (k16 ^ (rloc & 7));
    uint4* base = g_A + mtile * A_MT_U4;
    base[(half)     * A_CH_U4 + off16] = hi.q;   // hi (pairs B hi)
    base[(2 + half) * A_CH_U4 + off16] = hi.q;   // hi (pairs B lo)
    base[(4 + half) * A_CH_U4 + off16] = lo.q;   // lo (pairs B hi)
}

// ---------------------------------------------------------------------------
// GEMM: grid (4 ntiles, 32 mtiles), block 256 (8 warps).
// ---------------------------------------------------------------------------
__device__ __forceinline__ void issue_chunk(uint32_t sbase, const uint4* gA,
                                            const uint4* gB, int c, int tid) {
    uint32_t dA = sbase + (c & 1) * 32768;
    uint32_t dB = dA + 16384;
    const uint4* sa = gA + c * A_CH_U4;
    const uint4* sb = gB + c * A_CH_U4;
    #pragma unroll
    for (int i = 0; i < 4; i++) CP16(dA + (tid + 256 * i) * 16, sa + tid + 256 * i);
    #pragma unroll
    for (int i = 0; i < 4; i++) CP16(dB + (tid + 256 * i) * 16, sb + tid + 256 * i);
    CP_COMMIT();
}

__global__ void __launch_bounds__(256)
gemm_kernel() {
    extern __shared__ __align__(1024) char smem[];
    uint32_t sbase = smem_u32(smem);
    const int tid = threadIdx.x;
    const int wid = tid >> 5, lane = tid & 31;
    const int ntile = blockIdx.x, mtile = blockIdx.y;

    const uint4* gA = g_A + mtile * A_MT_U4;
    const uint4* gB = g_B + ntile * B_NT_U4;

    const int m0 = (wid & 1) * 64;
    const int n0 = (wid >> 1) * 32;
    const int rowa  = m0 + (lane & 15);
    const int abase = (rowa >> 3) * 64 + (rowa & 7) * 8;
    const int aswz  = rowa & 7;
    const int akus  = lane >> 4;
    const int rowb  = n0 + (lane & 7) + ((lane >> 4) << 3);
    const int bbase = (rowb >> 3) * 64 + (rowb & 7) * 8;
    const int bswz  = rowb & 7;
    const int bkus  = (lane >> 3) & 1;

    float d[4][4][4];
    #pragma unroll
    for (int i = 0; i < 4; i++)
        #pragma unroll
        for (int j = 0; j < 4; j++)
            #pragma unroll
            for (int q = 0; q < 4; q++) d[i][j][q] = 0.0f;

    issue_chunk(sbase, gA, gB, 0, tid);

    #pragma unroll
    for (int c = 0; c < NCHUNK; c++) {
        if (c < NCHUNK - 1) {
            issue_chunk(sbase, gA, gB, c + 1, tid);
            CP_WAIT1();
        } else {
            CP_WAIT0();
        }
        __syncthreads();

        uint32_t aB = sbase + (c & 1) * 32768;
        uint32_t bB = aB + 16384;

        #pragma unroll
        for (int kk = 0; kk < 4; kk++) {
            uint32_t af[4][4];
            #pragma unroll
            for (int mf = 0; mf < 4; mf++) {
                uint32_t addr = aB + ((abase + mf * 128 +
                                       ((2 * kk + akus) ^ aswz)) << 4);
                LDSM4(af[mf][0], af[mf][1], af[mf][2], af[mf][3], addr);
            }
            uint32_t bf[2][4];
            #pragma unroll
            for (int h = 0; h < 2; h++) {
                uint32_t addr = bB + ((bbase + h * 128 +
                                       ((2 * kk + bkus) ^ bswz)) << 4);
                LDSM4(bf[h][0], bf[h][1], bf[h][2], bf[h][3], addr);
            }
            #pragma unroll
            for (int mf = 0; mf < 4; mf++)
                #pragma unroll
                for (int nf = 0; nf < 4; nf++)
                    MMA16816(d[mf][nf][0], d[mf][nf][1], d[mf][nf][2], d[mf][nf][3],
                             af[mf][0], af[mf][1], af[mf][2], af[mf][3],
                             bf[nf >> 1][(nf & 1) * 2], bf[nf >> 1][(nf & 1) * 2 + 1]);
        }
        __syncthreads();
    }

    const int rbase = mtile * 128 + m0 + (lane >> 2);
    const int cbase = ntile * 128 + n0 + 2 * (lane & 3);
    #pragma unroll
    for (int mf = 0; mf < 4; mf++)
        #pragma unroll
        for (int nf = 0; nf < 4; nf++) {
            int row = rbase + mf * 16;
            int col = cbase + nf * 8;
            *reinterpret_cast<float2*>(&g_acc[row * 512 + col]) =
                make_float2(d[mf][nf][0], d[mf][nf][1]);
            *reinterpret_cast<float2*>(&g_acc[(row + 8) * 512 + col]) =
                make_float2(d[mf][nf][2], d[mf][nf][3]);
        }
}

// ---------------------------------------------------------------------------
// Epilogue: hyperbolic math + softmax in base-2 space.
// grid 512 (8 rows each), block 256 (u = tid). One warp per row for softmax.
// ---------------------------------------------------------------------------
#define UPAD 257
#define EROWS 8
__global__ void __launch_bounds__(256)
epilogue_kernel(float* __restrict__ out) {
    __shared__ float slog[EROWS * UPAD];
    __shared__ float snv2[EROWS];
    const int u  = threadIdx.x;
    const int b0 = blockIdx.x * EROWS;

    if (u < EROWS) snv2[u] = g_nv2[b0 + u];

    float4 cs  = g_cons[u];
    float  nb2 = cs.x, bw = cs.y, sww = cs.z;
    float  beta = 1.0f - nb2;
    float  bsw  = beta * sww;
    float  twosww = 2.0f * sww;
    __syncthreads();

    float lg[EROWS];
    #pragma unroll
    for (int r = 0; r < EROWS; r++) {
        float xw  = g_acc[(b0 + r) * 512 + u];
        float xb  = g_acc[(b0 + r) * 512 + 256 + u];
        float nv2 = snv2[r];
        float xy = -xb;
        float t2 = 2.0f * xy;
        float alpha = 1.0f + t2 + nv2;
        float dd = 1.0f + t2 + nb2 * nv2;
        float num = 2.0f * beta * (beta * xw - alpha * bw);
        float smm_num = alpha * alpha * nb2 + 2.0f * alpha * beta * xy
                        + beta * beta * nv2;
        // arg = (num/dd) / ((1 - smm_num/dd^2) * beta * sww)
        //     = num*dd / ((dd^2 - smm_num) * beta * sww)     -- single division
        float arg = __fdividef(num * dd, (dd * dd - smm_num) * bsw);
        float s = arg + fast_sqrt(fmaf(arg, arg, 1.0f));
        // base-2 logits: softmax(c*ln s) == softmax2(c*log2 s)
        lg[r] = twosww * __log2f(s);
    }
    #pragma unroll
    for (int r = 0; r < EROWS; r++)
        slog[r * UPAD + u] = lg[r];
    __syncthreads();

    // softmax: warp w handles row w (8 warps, 8 rows)
    int r = u >> 5, lane = u & 31;
    float v[8];
    float m = -1e30f;
    #pragma unroll
    for (int j = 0; j < 8; j++) {
        v[j] = slog[r * UPAD + lane + 32 * j];
        m = fmaxf(m, v[j]);
    }
    #pragma unroll
    for (int sh = 16; sh > 0; sh >>= 1)
        m = fmaxf(m, __shfl_xor_sync(0xffffffffu, m, sh));
    float e[8], s = 0.0f;
    #pragma unroll
    for (int j = 0; j < 8; j++) { e[j] = exp2f(v[j] - m); s += e[j]; }
    #pragma unroll
    for (int sh = 16; sh > 0; sh >>= 1)
        s += __shfl_xor_sync(0xffffffffu, s, sh);
    float inv = __fdividef(1.0f, s);
    #pragma unroll
    for (int j = 0; j < 8; j++)
        out[(b0 + r) * UU + lane + 32 * j] = e[j] * inv;
}

// ---------------------------------------------------------------------------
extern "C" void kernel_launch(void* const* d_in, const int* in_sizes, int n_in,
                              void* d_out, int out_size) {
    const float* x    = (const float*)d_in[0];
    const float* W    = (const float*)d_in[1];
    const float* bias = (const float*)d_in[2];
    float* out = (float*)d_out;

    cudaFuncSetAttribute(gemm_kernel,
                         cudaFuncAttributeMaxDynamicSharedMemorySize, GEMM_SMEM);

    prepWB_kernel<<<UU, DD>>>(W, bias);
    prepA_kernel<<<BB / 16, 256>>>(x);
    gemm_kernel<<<dim3(4, 32), 256, GEMM_SMEM>>>();
    epilogue_kernel<<<BB / EROWS, 256>>>(out);
}